// round 1
// baseline (speedup 1.0000x reference)
#include <cuda_runtime.h>
#include <cstdint>

#define N_NODES 20000
#define F_DIM   512
#define S_SUB   6
#define NCOL    1024           // concat(re, im)
#define CHUNKS  100
#define ROWS_PER_CHUNK 200     // 100 * 200 = 20000
#define A_COEF  0.025f         // T * HSCALE
#define BN_EPS  1e-5f

// ---------------- scratch (device globals; no cudaMalloc allowed) ----------
__device__ float g_Y[N_NODES * NCOL];      // complex linear output (re | im)
__device__ float g_Z[N_NODES * NCOL];      // relu(evolved) (re | im)
__device__ float g_Cre[N_NODES * S_SUB];   // series coefficients
__device__ float g_Cim[N_NODES * S_SUB];
__device__ float g_Psum[CHUNKS * NCOL];
__device__ float g_Psq[CHUNKS * NCOL];
__device__ float g_scale[NCOL];
__device__ float g_shift[NCOL];

// ---------------- helpers ---------------------------------------------------
__device__ __forceinline__ uint32_t f2tf32(float x) {
    uint32_t r;
    asm("cvt.rna.tf32.f32 %0, %1;" : "=r"(r) : "f"(x));
    return r;
}

__device__ __forceinline__ void mma_tf32(float* c, const uint32_t* a, const uint32_t* b) {
    asm volatile(
        "mma.sync.aligned.m16n8k8.row.col.f32.tf32.tf32.f32 "
        "{%0,%1,%2,%3}, {%4,%5,%6,%7}, {%8,%9}, {%0,%1,%2,%3};"
        : "+f"(c[0]), "+f"(c[1]), "+f"(c[2]), "+f"(c[3])
        : "r"(a[0]), "r"(a[1]), "r"(a[2]), "r"(a[3]), "r"(b[0]), "r"(b[1]));
}

// ---------------- K1: per-node truncated exp(-iHt) center row --------------
__global__ void k_coef(const int* __restrict__ sub_adj) {
    int n = blockIdx.x * blockDim.x + threadIdx.x;
    if (n >= N_NODES) return;
    int A[S_SUB][S_SUB];
    float deg[S_SUB];
    const int* a = sub_adj + n * (S_SUB * S_SUB);
#pragma unroll
    for (int s = 0; s < S_SUB; s++) {
        int d = 0;
#pragma unroll
        for (int t = 0; t < S_SUB; t++) { A[s][t] = a[s * S_SUB + t]; d += A[s][t]; }
        deg[s] = (float)d;
    }
    // M = -i * A_COEF * L, L = diag(deg) - A.  term/res as row vectors.
    float tr[S_SUB], ti[S_SUB], rr[S_SUB], ri[S_SUB];
#pragma unroll
    for (int t = 0; t < S_SUB; t++) { tr[t] = (t == 0) ? 1.f : 0.f; ti[t] = 0.f; rr[t] = tr[t]; ri[t] = 0.f; }
#pragma unroll
    for (int k = 1; k <= 4; k++) {
        float nr[S_SUB], ni[S_SUB];
        float invk = 1.0f / (float)k;
#pragma unroll
        for (int t = 0; t < S_SUB; t++) {
            float sr = 0.f, si = 0.f;
#pragma unroll
            for (int s = 0; s < S_SUB; s++) {
                float L = ((s == t) ? deg[s] : 0.f) - (float)A[s][t];
                float m = A_COEF * L;              // term * (-i m): re += m*ti, im -= m*tr
                sr += m * ti[s];
                si -= m * tr[s];
            }
            nr[t] = sr * invk; ni[t] = si * invk;
        }
#pragma unroll
        for (int t = 0; t < S_SUB; t++) { tr[t] = nr[t]; ti[t] = ni[t]; rr[t] += nr[t]; ri[t] += ni[t]; }
    }
#pragma unroll
    for (int t = 0; t < S_SUB; t++) { g_Cre[n * S_SUB + t] = rr[t]; g_Cim[n * S_SUB + t] = ri[t]; }
}

// ---------------- K2: tf32 GEMM  Y[20000,1024] = X[20000,512] @ [Wre|Wim] ---
#define BM 128
#define BN 128
#define BK 32

__global__ __launch_bounds__(256) void k_gemm(
    const float* __restrict__ X,
    const float* __restrict__ Wre, const float* __restrict__ Wim,
    const float* __restrict__ bre, const float* __restrict__ bim)
{
    __shared__ float As[BM][36];    // stride 36: conflict-free A-frag reads
    __shared__ float Bs[BK][136];   // stride 136: conflict-free B-frag reads

    const int tid = threadIdx.x;
    const int bm = blockIdx.x, bn = blockIdx.y;
    const float* W    = (bn < 4) ? Wre : Wim;
    const float* bias = (bn < 4) ? bre : bim;
    const int colOff  = (bn & 3) * BN;

    const int lane = tid & 31, w = tid >> 5;
    const int wm = w & 1, wn = w >> 1;           // 2x4 warp grid, warp tile 64x32
    const int gID = lane >> 2, tig = lane & 3;

    float acc[4][4][4];
#pragma unroll
    for (int m = 0; m < 4; m++)
#pragma unroll
        for (int n = 0; n < 4; n++)
#pragma unroll
            for (int i = 0; i < 4; i++) acc[m][n][i] = 0.f;

    const int ar = tid >> 3, ac = (tid & 7) * 4;   // A loader: 32 rows / pass
    const int br = tid >> 5, bc = (tid & 31) * 4;  // B loader: 8 rows / pass

    for (int kt = 0; kt < F_DIM; kt += BK) {
        // load A tile (guard M edge)
#pragma unroll
        for (int i = 0; i < 4; i++) {
            int r = ar + i * 32;
            int grow = bm * BM + r;
            float4 v = make_float4(0.f, 0.f, 0.f, 0.f);
            if (grow < N_NODES) v = *(const float4*)&X[(size_t)grow * F_DIM + kt + ac];
            As[r][ac + 0] = __uint_as_float(f2tf32(v.x));
            As[r][ac + 1] = __uint_as_float(f2tf32(v.y));
            As[r][ac + 2] = __uint_as_float(f2tf32(v.z));
            As[r][ac + 3] = __uint_as_float(f2tf32(v.w));
        }
        // load B tile
#pragma unroll
        for (int i = 0; i < 4; i++) {
            int r = br + i * 8;
            float4 v = *(const float4*)&W[(size_t)(kt + r) * F_DIM + colOff + bc];
            Bs[r][bc + 0] = __uint_as_float(f2tf32(v.x));
            Bs[r][bc + 1] = __uint_as_float(f2tf32(v.y));
            Bs[r][bc + 2] = __uint_as_float(f2tf32(v.z));
            Bs[r][bc + 3] = __uint_as_float(f2tf32(v.w));
        }
        __syncthreads();

#pragma unroll
        for (int k8 = 0; k8 < 4; k8++) {
            const int kk = k8 * 8;
            uint32_t afr[4][4], bfr[4][2];
#pragma unroll
            for (int m = 0; m < 4; m++) {
                int row = wm * 64 + m * 16;
                afr[m][0] = __float_as_uint(As[row + gID][kk + tig]);
                afr[m][1] = __float_as_uint(As[row + gID + 8][kk + tig]);
                afr[m][2] = __float_as_uint(As[row + gID][kk + tig + 4]);
                afr[m][3] = __float_as_uint(As[row + gID + 8][kk + tig + 4]);
            }
#pragma unroll
            for (int n = 0; n < 4; n++) {
                int col = wn * 32 + n * 8 + gID;
                bfr[n][0] = __float_as_uint(Bs[kk + tig][col]);
                bfr[n][1] = __float_as_uint(Bs[kk + tig + 4][col]);
            }
#pragma unroll
            for (int m = 0; m < 4; m++)
#pragma unroll
                for (int n = 0; n < 4; n++) mma_tf32(acc[m][n], afr[m], bfr[n]);
        }
        __syncthreads();
    }

    // epilogue: bias + store to g_Y
#pragma unroll
    for (int m = 0; m < 4; m++) {
        int row0 = bm * BM + wm * 64 + m * 16 + gID;
#pragma unroll
        for (int n = 0; n < 4; n++) {
            int lcol = wn * 32 + n * 8 + tig * 2;
            int gcol = bn * BN + lcol;
            float b0 = bias[colOff + lcol], b1 = bias[colOff + lcol + 1];
            if (row0 < N_NODES) {
                float2 v = make_float2(acc[m][n][0] + b0, acc[m][n][1] + b1);
                *(float2*)&g_Y[(size_t)row0 * NCOL + gcol] = v;
            }
            int row1 = row0 + 8;
            if (row1 < N_NODES) {
                float2 v = make_float2(acc[m][n][2] + b0, acc[m][n][3] + b1);
                *(float2*)&g_Y[(size_t)row1 * NCOL + gcol] = v;
            }
        }
    }
}

// ---------------- K3: gather + complex evolve + ReLU ------------------------
__global__ __launch_bounds__(128) void k_gather(const int* __restrict__ sub_nodes) {
    const int n = blockIdx.x;
    __shared__ float cr[S_SUB], ci[S_SUB];
    __shared__ int nb[S_SUB];
    if (threadIdx.x < S_SUB) {
        cr[threadIdx.x] = g_Cre[n * S_SUB + threadIdx.x];
        ci[threadIdx.x] = g_Cim[n * S_SUB + threadIdx.x];
        nb[threadIdx.x] = sub_nodes[n * S_SUB + threadIdx.x];
    }
    __syncthreads();
    const int f = threadIdx.x * 4;   // 128 threads * 4 = 512 features
    float4 ar = make_float4(0, 0, 0, 0), ai = make_float4(0, 0, 0, 0);
#pragma unroll
    for (int s = 0; s < S_SUB; s++) {
        const float* yrow = &g_Y[(size_t)nb[s] * NCOL];
        float4 yr = *(const float4*)&yrow[f];
        float4 yi = *(const float4*)&yrow[F_DIM + f];
        float c_r = cr[s], c_i = ci[s];
        ar.x += c_r * yr.x - c_i * yi.x; ai.x += c_r * yi.x + c_i * yr.x;
        ar.y += c_r * yr.y - c_i * yi.y; ai.y += c_r * yi.y + c_i * yr.y;
        ar.z += c_r * yr.z - c_i * yi.z; ai.z += c_r * yi.z + c_i * yr.z;
        ar.w += c_r * yr.w - c_i * yi.w; ai.w += c_r * yi.w + c_i * yr.w;
    }
    ar.x = fmaxf(ar.x, 0.f); ar.y = fmaxf(ar.y, 0.f); ar.z = fmaxf(ar.z, 0.f); ar.w = fmaxf(ar.w, 0.f);
    ai.x = fmaxf(ai.x, 0.f); ai.y = fmaxf(ai.y, 0.f); ai.z = fmaxf(ai.z, 0.f); ai.w = fmaxf(ai.w, 0.f);
    *(float4*)&g_Z[(size_t)n * NCOL + f] = ar;
    *(float4*)&g_Z[(size_t)n * NCOL + F_DIM + f] = ai;
}

// ---------------- K4a: deterministic per-chunk column partial sums ----------
__global__ __launch_bounds__(256) void k_colpart() {
    const int col = blockIdx.x * 256 + threadIdx.x;     // gridDim.x = 4
    const int r0  = blockIdx.y * ROWS_PER_CHUNK;
    float s = 0.f, ss = 0.f;
    for (int r = r0; r < r0 + ROWS_PER_CHUNK; r++) {
        float v = g_Z[(size_t)r * NCOL + col];
        s += v; ss += v * v;
    }
    g_Psum[blockIdx.y * NCOL + col] = s;
    g_Psq[blockIdx.y * NCOL + col]  = ss;
}

// ---------------- K4b: finalize mean/var -> fold gamma/beta -----------------
__global__ void k_colfin(const float* __restrict__ gr, const float* __restrict__ br,
                         const float* __restrict__ gi, const float* __restrict__ bi) {
    const int f = threadIdx.x;  // 1024 threads
    float s = 0.f, ss = 0.f;
    for (int c = 0; c < CHUNKS; c++) { s += g_Psum[c * NCOL + f]; ss += g_Psq[c * NCOL + f]; }
    const float invN = 1.0f / (float)N_NODES;
    float mean = s * invN;
    float var  = ss * invN - mean * mean;
    float inv  = rsqrtf(var + BN_EPS);
    float gamma = (f < F_DIM) ? gr[f] : gi[f - F_DIM];
    float beta  = (f < F_DIM) ? br[f] : bi[f - F_DIM];
    g_scale[f] = gamma * inv;
    g_shift[f] = beta - mean * gamma * inv;
}

// ---------------- K5: normalize + residual + write output -------------------
__global__ __launch_bounds__(512) void k_out(const float* __restrict__ X, float* __restrict__ out) {
    const int total = N_NODES * (NCOL / 4);
    for (int i = blockIdx.x * blockDim.x + threadIdx.x; i < total; i += gridDim.x * blockDim.x) {
        int row = i >> 8;          // NCOL/4 = 256 float4 per row
        int q   = i & 255;
        float4 z = *(const float4*)&g_Z[(size_t)i * 4];
        float4 sc = *(const float4*)&g_scale[q * 4];
        float4 sh = *(const float4*)&g_shift[q * 4];
        float4 r;
        r.x = z.x * sc.x + sh.x;
        r.y = z.y * sc.y + sh.y;
        r.z = z.z * sc.z + sh.z;
        r.w = z.w * sc.w + sh.w;
        if (q < 128) {  // real half: residual +x
            float4 xv = *(const float4*)&X[(size_t)row * F_DIM + q * 4];
            r.x += xv.x; r.y += xv.y; r.z += xv.z; r.w += xv.w;
        }
        *(float4*)&out[(size_t)i * 4] = r;
    }
}

// ---------------- launch ----------------------------------------------------
extern "C" void kernel_launch(void* const* d_in, const int* in_sizes, int n_in,
                              void* d_out, int out_size) {
    const float* x        = (const float*)d_in[0];
    const int*   sub_nodes= (const int*)  d_in[2];
    const int*   sub_adj  = (const int*)  d_in[3];
    const float* Wre      = (const float*)d_in[4];
    const float* Wim      = (const float*)d_in[5];
    const float* bre      = (const float*)d_in[6];
    const float* bim      = (const float*)d_in[7];
    const float* gr       = (const float*)d_in[8];
    const float* br       = (const float*)d_in[9];
    const float* gi       = (const float*)d_in[10];
    const float* bi       = (const float*)d_in[11];
    float* out = (float*)d_out;

    k_coef<<<(N_NODES + 255) / 256, 256>>>(sub_adj);
    dim3 ggrid((N_NODES + BM - 1) / BM, NCOL / BN);
    k_gemm<<<ggrid, 256>>>(x, Wre, Wim, bre, bim);
    k_gather<<<N_NODES, 128>>>(sub_nodes);
    k_colpart<<<dim3(4, CHUNKS), 256>>>();
    k_colfin<<<1, NCOL>>>(gr, br, gi, bi);
    k_out<<<640, 512>>>(x, out);
}